// round 14
// baseline (speedup 1.0000x reference)
#include <cuda_runtime.h>
#include <cuda_bf16.h>
#include <math.h>
#include <stdint.h>

// B=64 graphs, N=512 nodes, C=256. 8 clusters x 16 CTAs; cluster = group of
// 8 graphs, CTA = 16 channels. Weights smem-resident; activation DATA moves
// through L2 (.cg); exchange COMPLETION signaled by cluster mbarrier
// doorbells (arrive.release.cluster -> try_wait.parity.acquire.cluster).
#define FULLMASK 0xffffffffu
#define MAXE 48

typedef unsigned long long u64;

// Packed dual-FMA (sm_100+ f32x2 pipe).
__device__ __forceinline__ void fma2(u64& d, u64 a, u64 b) {
    asm("fma.rn.f32x2 %0, %1, %2, %0;" : "+l"(d) : "l"(a), "l"(b));
}
__device__ __forceinline__ float red2(u64 a) {
    float2 f = *reinterpret_cast<float2*>(&a);
    return f.x + f.y;
}

__device__ __forceinline__ uint32_t smem_u32(const void* p) {
    uint32_t a;
    asm("{ .reg .u64 t; cvta.to.shared.u64 t, %1; cvt.u32.u64 %0, t; }"
        : "=r"(a) : "l"(p));
    return a;
}

// ---- cluster mbarrier doorbells ----
#define MBAR_INIT(addr, cnt) \
    asm volatile("mbarrier.init.shared.b64 [%0], %1;" :: "r"(addr), "r"(cnt) : "memory")

// Arrive (release, cluster scope) on rank's copy of the barrier at the same
// smem offset. Cumulative release: orders this CTA's prior global stores
// (joined via __syncthreads) before the arrive.
__device__ __forceinline__ void mbar_arrive_rank(uint32_t laddr, uint32_t rank) {
    asm volatile(
        "{ .reg .b32 ra;\n\t"
        "mapa.shared::cluster.u32 ra, %0, %1;\n\t"
        "mbarrier.arrive.release.cluster.shared::cluster.b64 _, [ra]; }"
        :: "r"(laddr), "r"(rank) : "memory");
}

// Wait for completion of the phase with parity `par` (acquire, cluster scope).
__device__ __forceinline__ void mbar_wait_parity(uint32_t addr, uint32_t par) {
    uint32_t done;
    asm volatile(
        "{ .reg .pred p;\n\t"
        "mbarrier.try_wait.parity.acquire.cluster.shared::cta.b64 p, [%1], %2;\n\t"
        "selp.b32 %0, 1, 0, p; }"
        : "=r"(done) : "r"(addr), "r"(par) : "memory");
    if (!done) {
        asm volatile(
            "{ .reg .pred P1;\n\t"
            "WL_%=:\n\t"
            "mbarrier.try_wait.parity.acquire.cluster.shared::cta.b64 P1, [%0], %1, 0x989680;\n\t"
            "@P1 bra.uni WD_%=;\n\t"
            "bra.uni WL_%=;\n\t"
            "WD_%=: }"
            :: "r"(addr), "r"(par) : "memory");
    }
}

#define CLUSTER_SYNC_ONCE() do { \
    asm volatile("barrier.cluster.arrive.aligned;" ::: "memory"); \
    asm volatile("barrier.cluster.wait.aligned;"   ::: "memory"); \
} while (0)

// Scratch (device globals; allocation forbidden).
__device__ float ybuf[32768 * 256];              // cached mlp(h) per row
__device__ float hnew_buf[64 * 256];             // h_new of current node
__device__ float tbuf[64 * 256];                 // MLP layer-1 activations
__device__ int   el_src [2 * 512 * 64 * MAXE];   // compacted OLD-edge lists
__device__ int   el_cnt [2 * 512 * 64];
__device__ int   el_rcnt[2 * 512 * 64];          // # edges to node n-/+1
__device__ unsigned g_cnt[8 * 32];               // startup barrier counters
__device__ unsigned g_gen[8 * 32];               // startup barrier generations

// Startup-only group barrier (generation-based, replay-safe).
__device__ __forceinline__ void bar_arrive(int gb) {
    __threadfence();
    unsigned a = atomicAdd(&g_cnt[gb * 32], 1u);
    if (a == 15u) {
        g_cnt[gb * 32] = 0u;
        __threadfence();
        atomicAdd(&g_gen[gb * 32], 1u);
    }
}
__device__ __forceinline__ void bar_wait(int gb, unsigned target) {
    while ((int)(*(volatile unsigned*)&g_gen[gb * 32] - target) < 0) { }
    __threadfence();
}

// k-chunk interleave: chunk kc (0..63) at slot (kc%16)*4 + kc/16 so one warp
// instruction's 4 ks-chunks are bank-consecutive.
__device__ __forceinline__ int xslot(int kc) { return ((kc & 15) << 2) + (kc >> 4); }

// smem float4 offsets (x-buffers stride 69 f4 -> conflict-free gg-row reads)
#define O_WG4  0        // 96*64 GRU rows (0-47 ih, 48-95 hh), interleaved
#define O_W14  6144     // 16*64
#define O_W24  7168     // 16*64
#define O_XSA  8192     // 8*69  agg / h_new reload / t reload
#define O_XSH0 8744     // 8*69  h_old (even steps)
#define O_XSH1 9296     // 8*69  h_old (odd steps)
// float offsets (from float 39392 = 9848 f4)
#define F_GIS  39392    // 48*8
#define F_GHS0 39776    // 48*8
#define F_GHS1 40160    // 48*8
#define F_BIH  40544    // 48
#define F_BHH  40592    // 48
#define F_B1   40640    // 16
#define F_B2   40656    // 16
#define F_MBAR 40672    // 3 mbarriers (8B each), 8B-aligned (40672*4 % 8 == 0)
#define SMEM_FLOATS 40688
#define SMEM_BYTES  (SMEM_FLOATS * 4)

__device__ __forceinline__ float4 f4add(float4 a, float4 b) {
    a.x += b.x; a.y += b.y; a.z += b.z; a.w += b.w; return a;
}

__global__ void __launch_bounds__(512, 1)
gnn_kernel(float* __restrict__ hx,
           const float* __restrict__ W1, const float* __restrict__ b1,
           const float* __restrict__ W2, const float* __restrict__ b2,
           const float* __restrict__ w_ih, const float* __restrict__ b_ih,
           const float* __restrict__ w_hh, const float* __restrict__ b_hh,
           const int* __restrict__ src_f, const int* __restrict__ gid_f,
           const float* __restrict__ msk_f,
           const int* __restrict__ src_b, const int* __restrict__ gid_b,
           const float* __restrict__ msk_b,
           int Kf, int Kb)
{
    extern __shared__ float4 sm4[];
    float* smf = (float*)sm4;

    const int tid  = threadIdx.x;
    const int lane = tid & 31;
    const int wid  = tid >> 5;
    const int gb   = blockIdx.x >> 4;    // cluster/group: graphs [8gb, 8gb+8)
    const int cb   = blockIdx.x & 15;    // rank: channels [16cb, 16cb+16)
    const int g0   = gb * 8;
    const int ch0  = cb * 16;
    const int ks   = lane >> 3;          // k-split 0..3
    const int gg   = lane & 7;           // graph within group

    const uint32_t sbase = smem_u32(sm4);
    const uint32_t mb_h = sbase + F_MBAR * 4u;
    const uint32_t mb_t = mb_h + 8u;
    const uint32_t mb_y = mb_h + 16u;

    const unsigned base = *(volatile unsigned*)&g_gen[gb * 32];

    // ---- init mbarriers (every launch; all phases completed at prior exit) ----
    if (tid == 0) {
        MBAR_INIT(mb_h, 16);
        MBAR_INIT(mb_t, 16);
        MBAR_INIT(mb_y, 16);
    }

    // ---- stage weights into smem (once), k-chunk interleaved ----
    for (int idx = tid; idx < 96 * 64; idx += 512) {
        int row = idx >> 6, kc = idx & 63;
        const float* grow;
        if (row < 48) grow = w_ih + (size_t)((row >> 4) * 256 + ch0 + (row & 15)) * 256;
        else { int r = row - 48;
               grow = w_hh + (size_t)((r >> 4) * 256 + ch0 + (r & 15)) * 256; }
        sm4[O_WG4 + row * 64 + xslot(kc)] = *(const float4*)(grow + kc * 4);
    }
    for (int idx = tid; idx < 16 * 64; idx += 512) {
        int row = idx >> 6, kc = idx & 63;
        sm4[O_W14 + row * 64 + xslot(kc)] =
            *(const float4*)(W1 + (size_t)(ch0 + row) * 256 + kc * 4);
        sm4[O_W24 + row * 64 + xslot(kc)] =
            *(const float4*)(W2 + (size_t)(ch0 + row) * 256 + kc * 4);
    }
    if (tid < 48) {
        smf[F_BIH + tid] = b_ih[(tid >> 4) * 256 + ch0 + (tid & 15)];
        smf[F_BHH + tid] = b_hh[(tid >> 4) * 256 + ch0 + (tid & 15)];
    }
    if (tid < 16) { smf[F_B1 + tid] = b1[ch0 + tid]; smf[F_B2 + tid] = b2[ch0 + tid]; }

    // ---- one-time deterministic edge-list precompute (old vs recent) ----
    {
        int p  = cb + ((tid >> 3) << 4);          // (scan*512+step), p%16==cb
        int sc = p >> 9, st = p & 511;
        const int*   sA = sc ? src_b : src_f;
        const int*   gA = sc ? gid_b : gid_f;
        const float* mA = sc ? msk_b : msk_f;
        const int K = sc ? Kb : Kf;
        const int gw = g0 + (tid & 7);
        const int n  = sc ? (511 - st) : st;
        const int prow = (st > 0) ? ((sc ? n + 1 : n - 1) + gw * 512) : -1;
        size_t eo = (size_t)st * (size_t)K;
        int cnt = 0, rcnt = 0;
        int* dst = el_src + ((size_t)p * 64 + gw) * MAXE;
        for (int e = 0; e < K; e++) {
            if (__ldcg(&mA[eo + e]) != 0.f && __ldcg(&gA[eo + e]) == gw) {
                int s = __ldcg(&sA[eo + e]);
                if (s == prow) rcnt++;
                else { if (cnt < MAXE) dst[cnt] = s; cnt++; }
            }
        }
        el_cnt [(size_t)p * 64 + gw] = (cnt < MAXE) ? cnt : MAXE;
        el_rcnt[(size_t)p * 64 + gw] = rcnt;
    }
    __syncthreads();
    if (tid == 0) bar_arrive(gb);
    if (tid == 0) bar_wait(gb, base + 1);
    __syncthreads();
    // mbarrier inits visible cluster-wide before any remote arrive.
    CLUSTER_SYNC_ONCE();

    // per-warp prefetch registers
    int   cntR = 0, rcR = 0, i0R = 0, i1R = 0;    // teamG: edge list
    float4 hp0 = make_float4(0.f,0.f,0.f,0.f), hp1 = hp0;  // teamH: next h row

    for (int scan = 0; scan < 2; ++scan) {
        // ===== prime: load h(n0), gh(n0). (Visibility of previous scan's hx
        // writes is carried by step-511's h/t acquires; no extra wait needed.)
        __syncthreads();
        {
            int n0 = scan ? 511 : 0;
            int g = tid >> 6, kc = tid & 63;
            sm4[O_XSH0 + g * 69 + xslot(kc)] =
                __ldcg((const float4*)(hx + ((size_t)(g0 + g) * 512 + n0) * 256) + kc);
        }
        __syncthreads();
        {   // gh(n0): 16 warps x 3 rows -> GHS0
            const float4* xb = sm4 + O_XSH0 + gg * 69;
            const float4* wb = sm4 + O_WG4 + (48 + wid * 3) * 64;
            u64 acc[3] = {0ull, 0ull, 0ull};
            #pragma unroll
            for (int c = 0; c < 16; c++) {
                float4 xv = xb[c * 4 + ks];
                ulonglong2 xu = *reinterpret_cast<ulonglong2*>(&xv);
                #pragma unroll
                for (int i = 0; i < 3; i++) {
                    float4 wv = wb[i * 64 + c * 4 + ks];
                    ulonglong2 wu = *reinterpret_cast<ulonglong2*>(&wv);
                    fma2(acc[i], xu.x, wu.x);
                    fma2(acc[i], xu.y, wu.y);
                }
            }
            float af[3];
            #pragma unroll
            for (int i = 0; i < 3; i++) af[i] = red2(acc[i]);
            #pragma unroll
            for (int off = 8; off <= 16; off <<= 1)
                #pragma unroll
                for (int i = 0; i < 3; i++)
                    af[i] += __shfl_xor_sync(FULLMASK, af[i], off);
            if (lane < 8)
                #pragma unroll
                for (int i = 0; i < 3; i++)
                    smf[F_GHS0 + (wid * 3 + i) * 8 + lane] = af[i];
        }
        // prime prefetches
        if (wid < 8) {
            size_t pi = (size_t)(scan * 512) * 64 + (g0 + wid);
            const int* lst = el_src + pi * MAXE;
            cntR = __ldcg(&el_cnt[pi]);
            rcR  = __ldcg(&el_rcnt[pi]);
            i0R = __ldcg(lst + lane);
            i1R = (lane + 32 < MAXE) ? __ldcg(lst + lane + 32) : 0;
        } else {
            int n1 = scan ? 510 : 1;
            const float4* hr =
                (const float4*)(hx + ((size_t)(g0 + wid - 8) * 512 + n1) * 256);
            hp0 = __ldcg(hr + lane); hp1 = __ldcg(hr + 32 + lane);
        }
        __syncthreads();

        for (int step = 0; step < 512; ++step) {
            const int n   = scan ? (511 - step) : step;
            const int idx = scan * 512 + step;         // global phase index
            const uint32_t pi_cur = (uint32_t)(idx & 1);
            const int cur = step & 1;
            const int oxsh_cur = cur ? O_XSH1 : O_XSH0;
            const int oxsh_nxt = cur ? O_XSH0 : O_XSH1;
            float* ghs_cur = smf + (cur ? F_GHS1 : F_GHS0);
            float* ghs_nxt = smf + (cur ? F_GHS0 : F_GHS1);

            // ========== Phase A (parallel teams) ==========
            if (wid < 8) {
                // teamG: gather OLD edges (rows >= 2 steps stale, visible via
                // earlier acquires), then doorbell-wait y(prev), then recent.
                const int g = wid, gw = g0 + g;
                float4 a0 = make_float4(0.f,0.f,0.f,0.f);
                float4 a1 = make_float4(0.f,0.f,0.f,0.f);
                for (int i = 0; i < cntR; i++) {
                    int sel = (i < 32) ? i0R : i1R;
                    int row = __shfl_sync(FULLMASK, sel, i & 31);
                    const float4* yr = (const float4*)(ybuf + (size_t)row * 256);
                    a0 = f4add(a0, __ldcg(yr + lane));
                    a1 = f4add(a1, __ldcg(yr + 32 + lane));
                }
                if (idx > 0)                            // y phase idx-1
                    mbar_wait_parity(mb_y, pi_cur ^ 1u);
                if (rcR > 0) {
                    int prow = (scan ? n + 1 : n - 1) + gw * 512;
                    const float4* yr = (const float4*)(ybuf + (size_t)prow * 256);
                    float rc = (float)rcR;
                    float4 v0 = __ldcg(yr + lane), v1 = __ldcg(yr + 32 + lane);
                    a0.x = fmaf(rc, v0.x, a0.x); a0.y = fmaf(rc, v0.y, a0.y);
                    a0.z = fmaf(rc, v0.z, a0.z); a0.w = fmaf(rc, v0.w, a0.w);
                    a1.x = fmaf(rc, v1.x, a1.x); a1.y = fmaf(rc, v1.y, a1.y);
                    a1.z = fmaf(rc, v1.z, a1.z); a1.w = fmaf(rc, v1.w, a1.w);
                }
                sm4[O_XSA + g * 69 + xslot(lane)]      = a0;
                sm4[O_XSA + g * 69 + xslot(lane + 32)] = a1;
                if (step + 1 < 512) {
                    size_t pi = (size_t)(scan * 512 + step + 1) * 64 + gw;
                    const int* lst = el_src + pi * MAXE;
                    cntR = __ldcg(&el_cnt[pi]);
                    rcR  = __ldcg(&el_rcnt[pi]);
                    i0R = __ldcg(lst + lane);
                    i1R = (lane + 32 < MAXE) ? __ldcg(lst + lane + 32) : 0;
                }
            } else if (step + 1 < 512) {
                // teamH: publish h(n+1), gh(n+1) -> GHS[nxt]
                const int w = wid - 8;
                sm4[oxsh_nxt + w * 69 + xslot(lane)]      = hp0;
                sm4[oxsh_nxt + w * 69 + xslot(lane + 32)] = hp1;
                asm volatile("bar.sync 2, 256;" ::: "memory");
                const float4* xb = sm4 + oxsh_nxt + gg * 69;
                const float4* wb = sm4 + O_WG4 + (48 + w * 6) * 64;
                u64 acc[6] = {0ull,0ull,0ull,0ull,0ull,0ull};
                #pragma unroll
                for (int c = 0; c < 16; c++) {
                    float4 xv = xb[c * 4 + ks];
                    ulonglong2 xu = *reinterpret_cast<ulonglong2*>(&xv);
                    #pragma unroll
                    for (int i = 0; i < 6; i++) {
                        float4 wv = wb[i * 64 + c * 4 + ks];
                        ulonglong2 wu = *reinterpret_cast<ulonglong2*>(&wv);
                        fma2(acc[i], xu.x, wu.x);
                        fma2(acc[i], xu.y, wu.y);
                    }
                }
                float af[6];
                #pragma unroll
                for (int i = 0; i < 6; i++) af[i] = red2(acc[i]);
                #pragma unroll
                for (int off = 8; off <= 16; off <<= 1)
                    #pragma unroll
                    for (int i = 0; i < 6; i++)
                        af[i] += __shfl_xor_sync(FULLMASK, af[i], off);
                if (lane < 8)
                    #pragma unroll
                    for (int i = 0; i < 6; i++)
                        ghs_nxt[(w * 6 + i) * 8 + lane] = af[i];
                if (step + 2 < 512) {      // prefetch h(n+/-2)
                    int npp = scan ? (n - 2) : (n + 2);
                    const float4* hr =
                        (const float4*)(hx + ((size_t)(g0 + w) * 512 + npp) * 256);
                    hp0 = __ldcg(hr + lane); hp1 = __ldcg(hr + 32 + lane);
                }
            }
            __syncthreads();

            // ========== Phase B: gi GEMM, all 16 warps x 3 rows ==========
            {
                const float4* xb = sm4 + O_XSA + gg * 69;
                const float4* wb = sm4 + O_WG4 + (wid * 3) * 64;
                u64 acc[3] = {0ull, 0ull, 0ull};
                #pragma unroll
                for (int c = 0; c < 16; c++) {
                    float4 xv = xb[c * 4 + ks];
                    ulonglong2 xu = *reinterpret_cast<ulonglong2*>(&xv);
                    #pragma unroll
                    for (int i = 0; i < 3; i++) {
                        float4 wv = wb[i * 64 + c * 4 + ks];
                        ulonglong2 wu = *reinterpret_cast<ulonglong2*>(&wv);
                        fma2(acc[i], xu.x, wu.x);
                        fma2(acc[i], xu.y, wu.y);
                    }
                }
                float af[3];
                #pragma unroll
                for (int i = 0; i < 3; i++) af[i] = red2(acc[i]);
                #pragma unroll
                for (int off = 8; off <= 16; off <<= 1)
                    #pragma unroll
                    for (int i = 0; i < 3; i++)
                        af[i] += __shfl_xor_sync(FULLMASK, af[i], off);
                if (lane < 8)
                    #pragma unroll
                    for (int i = 0; i < 3; i++)
                        smf[F_GIS + (wid * 3 + i) * 8 + lane] = af[i];
            }
            __syncthreads();

            // ========== Phase C: gate combine -> h_new + doorbell ==========
            if (tid < 128) {
                int g = tid >> 4, c = tid & 15;
                const float* gis = smf + F_GIS;
                float rr = gis[c * 8 + g] + smf[F_BIH + c]
                         + ghs_cur[c * 8 + g] + smf[F_BHH + c];
                float zz = gis[(16 + c) * 8 + g] + smf[F_BIH + 16 + c]
                         + ghs_cur[(16 + c) * 8 + g] + smf[F_BHH + 16 + c];
                float in_ = gis[(32 + c) * 8 + g] + smf[F_BIH + 32 + c];
                float hn  = ghs_cur[(32 + c) * 8 + g] + smf[F_BHH + 32 + c];
                float r = 1.f / (1.f + __expf(-rr));
                float z = 1.f / (1.f + __expf(-zz));
                float nn = tanhf(in_ + r * hn);
                int k = ch0 + c, kc = k >> 2;
                float ho = smf[(oxsh_cur + g * 69 + xslot(kc)) * 4 + (k & 3)];
                float hv = (1.f - z) * nn + z * ho;
                __stcg(&hnew_buf[(size_t)(g0 + g) * 256 + k], hv);
                __stcg(&hx[((size_t)(g0 + g) * 512 + n) * 256 + k], hv);
            }
            __syncthreads();
            if (tid < 16) mbar_arrive_rank(mb_h, (uint32_t)tid);
            mbar_wait_parity(mb_h, pi_cur);            // full h_new visible

            // reload h_new -> XSA
            {
                int g = tid >> 6, kc = tid & 63;
                sm4[O_XSA + g * 69 + xslot(kc)] =
                    __ldcg((const float4*)(hnew_buf + (size_t)(g0 + g) * 256) + kc);
            }
            __syncthreads();

            // ========== Phase D: M1 t = relu(W1 h_new + b1), row/warp ==========
            {
                const float4* xb = sm4 + O_XSA + gg * 69;
                const float4* wb = sm4 + O_W14 + wid * 64;
                u64 acc = 0ull;
                #pragma unroll
                for (int c = 0; c < 16; c++) {
                    float4 xv = xb[c * 4 + ks];
                    ulonglong2 xu = *reinterpret_cast<ulonglong2*>(&xv);
                    float4 wv = wb[c * 4 + ks];
                    ulonglong2 wu = *reinterpret_cast<ulonglong2*>(&wv);
                    fma2(acc, xu.x, wu.x);
                    fma2(acc, xu.y, wu.y);
                }
                float af = red2(acc);
                af += __shfl_xor_sync(FULLMASK, af, 8);
                af += __shfl_xor_sync(FULLMASK, af, 16);
                if (lane < 8)
                    __stcg(&tbuf[(size_t)(g0 + lane) * 256 + ch0 + wid],
                           fmaxf(af + smf[F_B1 + wid], 0.f));
            }
            __syncthreads();
            if (tid < 16) mbar_arrive_rank(mb_t, (uint32_t)tid);
            mbar_wait_parity(mb_t, pi_cur);            // full t visible

            // reload t -> XSA
            {
                int g = tid >> 6, kc = tid & 63;
                sm4[O_XSA + g * 69 + xslot(kc)] =
                    __ldcg((const float4*)(tbuf + (size_t)(g0 + g) * 256) + kc);
            }
            __syncthreads();

            // ========== Phase E: M2 y = relu(W2 t + b2) + doorbell ==========
            {
                const float4* xb = sm4 + O_XSA + gg * 69;
                const float4* wb = sm4 + O_W24 + wid * 64;
                u64 acc = 0ull;
                #pragma unroll
                for (int c = 0; c < 16; c++) {
                    float4 xv = xb[c * 4 + ks];
                    ulonglong2 xu = *reinterpret_cast<ulonglong2*>(&xv);
                    float4 wv = wb[c * 4 + ks];
                    ulonglong2 wu = *reinterpret_cast<ulonglong2*>(&wv);
                    fma2(acc, xu.x, wu.x);
                    fma2(acc, xu.y, wu.y);
                }
                float af = red2(acc);
                af += __shfl_xor_sync(FULLMASK, af, 8);
                af += __shfl_xor_sync(FULLMASK, af, 16);
                if (lane < 8)
                    __stcg(&ybuf[((size_t)(g0 + lane) * 512 + n) * 256 + ch0 + wid],
                           fmaxf(af + smf[F_B2 + wid], 0.f));
            }
            __syncthreads();
            if (tid < 16) mbar_arrive_rank(mb_y, (uint32_t)tid);
            // no wait here: next step's teamG tests y parity
        }
        // drain the final y phase of this scan so parity stays consistent and
        // all peers' y/t/h of step 511 are visible before the next prime.
        mbar_wait_parity(mb_y, (uint32_t)((scan * 512 + 511) & 1));
    }
}

extern "C" void kernel_launch(void* const* d_in, const int* in_sizes, int n_in,
                              void* d_out, int out_size) {
    const float* x    = (const float*)d_in[0];
    const float* W1   = (const float*)d_in[1];
    const float* b1   = (const float*)d_in[2];
    const float* W2   = (const float*)d_in[3];
    const float* b2   = (const float*)d_in[4];
    const float* w_ih = (const float*)d_in[5];
    const float* b_ih = (const float*)d_in[6];
    const float* w_hh = (const float*)d_in[7];
    const float* b_hh = (const float*)d_in[8];
    const int*   src_f = (const int*)d_in[9];
    const int*   gid_f = (const int*)d_in[10];
    const float* msk_f = (const float*)d_in[11];
    const int*   src_b = (const int*)d_in[12];
    const int*   gid_b = (const int*)d_in[13];
    const float* msk_b = (const float*)d_in[14];
    float* hx = (float*)d_out;

    int Kf = in_sizes[9] / 512;
    int Kb = in_sizes[12] / 512;

    cudaMemcpyAsync(hx, x, (size_t)32768 * 256 * sizeof(float),
                    cudaMemcpyDeviceToDevice);

    cudaFuncSetAttribute(gnn_kernel, cudaFuncAttributeMaxDynamicSharedMemorySize,
                         SMEM_BYTES);
    cudaFuncSetAttribute(gnn_kernel, cudaFuncAttributeNonPortableClusterSizeAllowed, 1);

    cudaLaunchConfig_t cfg = {};
    cfg.gridDim = dim3(128, 1, 1);
    cfg.blockDim = dim3(512, 1, 1);
    cfg.dynamicSmemBytes = SMEM_BYTES;
    cfg.stream = 0;
    cudaLaunchAttribute attr[1];
    attr[0].id = cudaLaunchAttributeClusterDimension;
    attr[0].val.clusterDim.x = 16;
    attr[0].val.clusterDim.y = 1;
    attr[0].val.clusterDim.z = 1;
    cfg.attrs = attr;
    cfg.numAttrs = 1;
    cudaLaunchKernelEx(&cfg, gnn_kernel, hx, W1, b1, W2, b2, w_ih, b_ih, w_hh, b_hh,
                       src_f, gid_f, msk_f, src_b, gid_b, msk_b, Kf, Kb);
}

// round 15
// speedup vs baseline: 2.3258x; 2.3258x over previous
#include <cuda_runtime.h>
#include <cuda_bf16.h>
#include <math.h>
#include <stdint.h>

// B=64 graphs, N=512 nodes, C=256. 8 groups x 16 CTAs; group = 8 graphs,
// CTA = 16 channels. Weights smem-resident; activations exchanged via L2
// with monotone release/acquire flags (atomic barrier only at startup).
// Old-edge gather for step s+1 is overlapped with step s's h-exchange.
#define FULLMASK 0xffffffffu
#define MAXE 48

typedef unsigned long long u64;

// Packed dual-FMA (sm_100+ f32x2 pipe).
__device__ __forceinline__ void fma2(u64& d, u64 a, u64 b) {
    asm("fma.rn.f32x2 %0, %1, %2, %0;" : "+l"(d) : "l"(a), "l"(b));
}
__device__ __forceinline__ float red2(u64 a) {
    float2 f = *reinterpret_cast<float2*>(&a);
    return f.x + f.y;
}

// Scoped acquire/release flag ops.
__device__ __forceinline__ unsigned ld_acq(const unsigned* p) {
    unsigned v;
    asm volatile("ld.acquire.gpu.u32 %0, [%1];" : "=r"(v) : "l"(p) : "memory");
    return v;
}
__device__ __forceinline__ void st_rel(unsigned* p, unsigned v) {
    asm volatile("st.release.gpu.u32 [%0], %1;" :: "l"(p), "r"(v) : "memory");
}

// Scratch (device globals; allocation forbidden).
__device__ float ybuf[32768 * 256];              // cached mlp(h) per row
__device__ float hnew_buf[64 * 256];             // h_new of current node
__device__ float tbuf[64 * 256];                 // MLP layer-1 activations
__device__ int   el_src [2 * 512 * 64 * MAXE];   // compacted OLD-edge lists
__device__ int   el_cnt [2 * 512 * 64];
__device__ int   el_rcnt[2 * 512 * 64];          // # edges to node n-/+1
__device__ unsigned g_cnt[8 * 32];               // startup barrier counters
__device__ unsigned g_gen[8 * 32];               // startup barrier generations
__device__ unsigned hflag[8 * 16 * 8];           // padded monotone tags
__device__ unsigned tflag[8 * 16 * 8];
__device__ unsigned yflag[8 * 16 * 8];
#define FIDX(gb, r) (((gb) * 16 + (r)) * 8)

// Startup-only group barrier (generation-based, replay-safe).
__device__ __forceinline__ void bar_arrive(int gb) {
    __threadfence();
    unsigned a = atomicAdd(&g_cnt[gb * 32], 1u);
    if (a == 15u) {
        g_cnt[gb * 32] = 0u;
        __threadfence();
        atomicAdd(&g_gen[gb * 32], 1u);
    }
}
__device__ __forceinline__ void bar_wait(int gb, unsigned target) {
    while ((int)(*(volatile unsigned*)&g_gen[gb * 32] - target) < 0) { }
    __threadfence();
}

// k-chunk interleave: chunk kc (0..63) at slot (kc%16)*4 + kc/16 so one warp
// instruction's 4 ks-chunks are bank-consecutive.
__device__ __forceinline__ int xslot(int kc) { return ((kc & 15) << 2) + (kc >> 4); }

// smem float4 offsets (x-buffers stride 69 f4 -> conflict-free gg-row reads)
#define O_WG4  0        // 96*64 GRU rows (0-47 ih, 48-95 hh), interleaved
#define O_W14  6144     // 16*64
#define O_W24  7168     // 16*64
#define O_XSA  8192     // 8*69  agg / h_new reload / t reload
#define O_XSH0 8744     // 8*69  h_old (even steps)
#define O_XSH1 9296     // 8*69  h_old (odd steps)
// float offsets (from float 39392 = 9848 f4)
#define F_GIS  39392    // 48*8
#define F_GHS0 39776    // 48*8
#define F_GHS1 40160    // 48*8
#define F_BIH  40544    // 48
#define F_BHH  40592    // 48
#define F_B1   40640    // 16
#define F_B2   40656    // 16
#define SMEM_FLOATS 40672
#define SMEM_BYTES  (SMEM_FLOATS * 4)

__device__ __forceinline__ float4 f4add(float4 a, float4 b) {
    a.x += b.x; a.y += b.y; a.z += b.z; a.w += b.w; return a;
}

__global__ void __launch_bounds__(512, 1)
gnn_kernel(float* __restrict__ hx,
           const float* __restrict__ W1, const float* __restrict__ b1,
           const float* __restrict__ W2, const float* __restrict__ b2,
           const float* __restrict__ w_ih, const float* __restrict__ b_ih,
           const float* __restrict__ w_hh, const float* __restrict__ b_hh,
           const int* __restrict__ src_f, const int* __restrict__ gid_f,
           const float* __restrict__ msk_f,
           const int* __restrict__ src_b, const int* __restrict__ gid_b,
           const float* __restrict__ msk_b,
           int Kf, int Kb)
{
    extern __shared__ float4 sm4[];
    float* smf = (float*)sm4;

    const int tid  = threadIdx.x;
    const int lane = tid & 31;
    const int wid  = tid >> 5;
    const int gb   = blockIdx.x >> 4;    // group: graphs [8gb, 8gb+8)
    const int cb   = blockIdx.x & 15;    // channel block: [16cb, 16cb+16)
    const int g0   = gb * 8;
    const int ch0  = cb * 16;
    const int ks   = lane >> 3;          // k-split 0..3
    const int gg   = lane & 7;           // graph within group

    const unsigned base = *(volatile unsigned*)&g_gen[gb * 32];

    // ---- stage weights into smem (once), k-chunk interleaved ----
    for (int idx = tid; idx < 96 * 64; idx += 512) {
        int row = idx >> 6, kc = idx & 63;
        const float* grow;
        if (row < 48) grow = w_ih + (size_t)((row >> 4) * 256 + ch0 + (row & 15)) * 256;
        else { int r = row - 48;
               grow = w_hh + (size_t)((r >> 4) * 256 + ch0 + (r & 15)) * 256; }
        sm4[O_WG4 + row * 64 + xslot(kc)] = *(const float4*)(grow + kc * 4);
    }
    for (int idx = tid; idx < 16 * 64; idx += 512) {
        int row = idx >> 6, kc = idx & 63;
        sm4[O_W14 + row * 64 + xslot(kc)] =
            *(const float4*)(W1 + (size_t)(ch0 + row) * 256 + kc * 4);
        sm4[O_W24 + row * 64 + xslot(kc)] =
            *(const float4*)(W2 + (size_t)(ch0 + row) * 256 + kc * 4);
    }
    if (tid < 48) {
        smf[F_BIH + tid] = b_ih[(tid >> 4) * 256 + ch0 + (tid & 15)];
        smf[F_BHH + tid] = b_hh[(tid >> 4) * 256 + ch0 + (tid & 15)];
    }
    if (tid < 16) { smf[F_B1 + tid] = b1[ch0 + tid]; smf[F_B2 + tid] = b2[ch0 + tid]; }

    // ---- reset this CTA's flags (ordered before use by startup barrier) ----
    if (tid == 0) {
        st_rel(&hflag[FIDX(gb, cb)], 0u);
        st_rel(&tflag[FIDX(gb, cb)], 0u);
        st_rel(&yflag[FIDX(gb, cb)], 0u);
    }

    // ---- one-time deterministic edge-list precompute (old vs recent) ----
    {
        int p  = cb + ((tid >> 3) << 4);          // (scan*512+step), p%16==cb
        int sc = p >> 9, st = p & 511;
        const int*   sA = sc ? src_b : src_f;
        const int*   gA = sc ? gid_b : gid_f;
        const float* mA = sc ? msk_b : msk_f;
        const int K = sc ? Kb : Kf;
        const int gw = g0 + (tid & 7);
        const int n  = sc ? (511 - st) : st;
        const int prow = (st > 0) ? ((sc ? n + 1 : n - 1) + gw * 512) : -1;
        size_t eo = (size_t)st * (size_t)K;
        int cnt = 0, rcnt = 0;
        int* dst = el_src + ((size_t)p * 64 + gw) * MAXE;
        for (int e = 0; e < K; e++) {
            if (__ldcg(&mA[eo + e]) != 0.f && __ldcg(&gA[eo + e]) == gw) {
                int s = __ldcg(&sA[eo + e]);
                if (s == prow) rcnt++;
                else { if (cnt < MAXE) dst[cnt] = s; cnt++; }
            }
        }
        el_cnt [(size_t)p * 64 + gw] = (cnt < MAXE) ? cnt : MAXE;
        el_rcnt[(size_t)p * 64 + gw] = rcnt;
    }
    __syncthreads();
    if (tid == 0) bar_arrive(gb);
    if (tid == 0) bar_wait(gb, base + 1);
    __syncthreads();

    // per-warp prefetch registers
    int   cntR = 0, rcR = 0, i0R = 0, i1R = 0;    // teamG: edge list (next step)
    float4 aG0 = make_float4(0.f,0.f,0.f,0.f), aG1 = aG0;  // carried old-gather
    float4 hp0 = make_float4(0.f,0.f,0.f,0.f), hp1 = hp0;  // teamH: next h row

    for (int scan = 0; scan < 2; ++scan) {
        // ===== prime: wait all peers' h of previous scan, load h(n0), gh(n0) =====
        {
            unsigned wt = (unsigned)(scan * 512);
            if (wid == 0) {
                if (lane < 16)
                    while ((int)(ld_acq(&hflag[FIDX(gb, lane)]) - wt) < 0) { }
                __syncwarp();
            }
        }
        __syncthreads();
        {
            int n0 = scan ? 511 : 0;
            int g = tid >> 6, kc = tid & 63;
            sm4[O_XSH0 + g * 69 + xslot(kc)] =
                __ldcg((const float4*)(hx + ((size_t)(g0 + g) * 512 + n0) * 256) + kc);
        }
        __syncthreads();
        {   // gh(n0): 16 warps x 3 rows -> GHS0
            const float4* xb = sm4 + O_XSH0 + gg * 69;
            const float4* wb = sm4 + O_WG4 + (48 + wid * 3) * 64;
            u64 acc[3] = {0ull, 0ull, 0ull};
            #pragma unroll
            for (int c = 0; c < 16; c++) {
                float4 xv = xb[c * 4 + ks];
                ulonglong2 xu = *reinterpret_cast<ulonglong2*>(&xv);
                #pragma unroll
                for (int i = 0; i < 3; i++) {
                    float4 wv = wb[i * 64 + c * 4 + ks];
                    ulonglong2 wu = *reinterpret_cast<ulonglong2*>(&wv);
                    fma2(acc[i], xu.x, wu.x);
                    fma2(acc[i], xu.y, wu.y);
                }
            }
            float af[3];
            #pragma unroll
            for (int i = 0; i < 3; i++) af[i] = red2(acc[i]);
            #pragma unroll
            for (int off = 8; off <= 16; off <<= 1)
                #pragma unroll
                for (int i = 0; i < 3; i++)
                    af[i] += __shfl_xor_sync(FULLMASK, af[i], off);
            if (lane < 8)
                #pragma unroll
                for (int i = 0; i < 3; i++)
                    smf[F_GHS0 + (wid * 3 + i) * 8 + lane] = af[i];
        }
        // prime prefetches + step-0 old gather (lists are empty for step 0 by
        // construction, but handled generally)
        if (wid < 8) {
            size_t pi = (size_t)(scan * 512) * 64 + (g0 + wid);
            const int* lst = el_src + pi * MAXE;
            cntR = __ldcg(&el_cnt[pi]);
            rcR  = __ldcg(&el_rcnt[pi]);
            i0R = __ldcg(lst + lane);
            i1R = (lane + 32 < MAXE) ? __ldcg(lst + lane + 32) : 0;
            aG0 = make_float4(0.f,0.f,0.f,0.f); aG1 = aG0;
            for (int i = 0; i < cntR; i++) {
                int sel = (i < 32) ? i0R : i1R;
                int row = __shfl_sync(FULLMASK, sel, i & 31);
                const float4* yr = (const float4*)(ybuf + (size_t)row * 256);
                aG0 = f4add(aG0, __ldcg(yr + lane));
                aG1 = f4add(aG1, __ldcg(yr + 32 + lane));
            }
        } else {
            int n1 = scan ? 510 : 1;
            const float4* hr =
                (const float4*)(hx + ((size_t)(g0 + wid - 8) * 512 + n1) * 256);
            hp0 = __ldcg(hr + lane); hp1 = __ldcg(hr + 32 + lane);
        }
        __syncthreads();

        for (int step = 0; step < 512; ++step) {
            const int n = scan ? (511 - step) : step;
            const unsigned tag = (unsigned)(scan * 512 + step + 1);
            const int cur = step & 1;
            const int oxsh_cur = cur ? O_XSH1 : O_XSH0;
            const int oxsh_nxt = cur ? O_XSH0 : O_XSH1;
            float* ghs_cur = smf + (cur ? F_GHS1 : F_GHS0);
            float* ghs_nxt = smf + (cur ? F_GHS0 : F_GHS1);

            // ========== Phase A (parallel teams) ==========
            if (wid < 8) {
                // teamG: old gather already carried in aG (done during the
                // previous step's h-exchange window). Wait y(prev), add the
                // recent row, store agg, prefetch next lists.
                const int g = wid, gw = g0 + g;
                float4 a0 = aG0, a1 = aG1;
                {   // per-warp wait: all 16 y(prev) slices published
                    unsigned wt = tag - 1u;
                    if (lane < 16)
                        while ((int)(ld_acq(&yflag[FIDX(gb, lane)]) - wt) < 0) { }
                    __syncwarp();
                }
                if (rcR > 0) {
                    int prow = (scan ? n + 1 : n - 1) + gw * 512;
                    const float4* yr = (const float4*)(ybuf + (size_t)prow * 256);
                    float rc = (float)rcR;
                    float4 v0 = __ldcg(yr + lane), v1 = __ldcg(yr + 32 + lane);
                    a0.x = fmaf(rc, v0.x, a0.x); a0.y = fmaf(rc, v0.y, a0.y);
                    a0.z = fmaf(rc, v0.z, a0.z); a0.w = fmaf(rc, v0.w, a0.w);
                    a1.x = fmaf(rc, v1.x, a1.x); a1.y = fmaf(rc, v1.y, a1.y);
                    a1.z = fmaf(rc, v1.z, a1.z); a1.w = fmaf(rc, v1.w, a1.w);
                }
                sm4[O_XSA + g * 69 + xslot(lane)]      = a0;
                sm4[O_XSA + g * 69 + xslot(lane + 32)] = a1;
                if (step + 1 < 512) {   // prefetch lists for step s+1
                    size_t pi = (size_t)(scan * 512 + step + 1) * 64 + gw;
                    const int* lst = el_src + pi * MAXE;
                    cntR = __ldcg(&el_cnt[pi]);
                    rcR  = __ldcg(&el_rcnt[pi]);
                    i0R = __ldcg(lst + lane);
                    i1R = (lane + 32 < MAXE) ? __ldcg(lst + lane + 32) : 0;
                }
            } else if (step + 1 < 512) {
                // teamH: publish h(n+1), gh(n+1) -> GHS[nxt]
                const int w = wid - 8;
                sm4[oxsh_nxt + w * 69 + xslot(lane)]      = hp0;
                sm4[oxsh_nxt + w * 69 + xslot(lane + 32)] = hp1;
                asm volatile("bar.sync 2, 256;" ::: "memory");
                const float4* xb = sm4 + oxsh_nxt + gg * 69;
                const float4* wb = sm4 + O_WG4 + (48 + w * 6) * 64;
                u64 acc[6] = {0ull,0ull,0ull,0ull,0ull,0ull};
                #pragma unroll
                for (int c = 0; c < 16; c++) {
                    float4 xv = xb[c * 4 + ks];
                    ulonglong2 xu = *reinterpret_cast<ulonglong2*>(&xv);
                    #pragma unroll
                    for (int i = 0; i < 6; i++) {
                        float4 wv = wb[i * 64 + c * 4 + ks];
                        ulonglong2 wu = *reinterpret_cast<ulonglong2*>(&wv);
                        fma2(acc[i], xu.x, wu.x);
                        fma2(acc[i], xu.y, wu.y);
                    }
                }
                float af[6];
                #pragma unroll
                for (int i = 0; i < 6; i++) af[i] = red2(acc[i]);
                #pragma unroll
                for (int off = 8; off <= 16; off <<= 1)
                    #pragma unroll
                    for (int i = 0; i < 6; i++)
                        af[i] += __shfl_xor_sync(FULLMASK, af[i], off);
                if (lane < 8)
                    #pragma unroll
                    for (int i = 0; i < 6; i++)
                        ghs_nxt[(w * 6 + i) * 8 + lane] = af[i];
                if (step + 2 < 512) {      // prefetch h(n+/-2)
                    int npp = scan ? (n - 2) : (n + 2);
                    const float4* hr =
                        (const float4*)(hx + ((size_t)(g0 + w) * 512 + npp) * 256);
                    hp0 = __ldcg(hr + lane); hp1 = __ldcg(hr + 32 + lane);
                }
            }
            __syncthreads();

            // ========== Phase B: gi GEMM, all 16 warps x 3 rows ==========
            {
                const float4* xb = sm4 + O_XSA + gg * 69;
                const float4* wb = sm4 + O_WG4 + (wid * 3) * 64;
                u64 acc[3] = {0ull, 0ull, 0ull};
                #pragma unroll
                for (int c = 0; c < 16; c++) {
                    float4 xv = xb[c * 4 + ks];
                    ulonglong2 xu = *reinterpret_cast<ulonglong2*>(&xv);
                    #pragma unroll
                    for (int i = 0; i < 3; i++) {
                        float4 wv = wb[i * 64 + c * 4 + ks];
                        ulonglong2 wu = *reinterpret_cast<ulonglong2*>(&wv);
                        fma2(acc[i], xu.x, wu.x);
                        fma2(acc[i], xu.y, wu.y);
                    }
                }
                float af[3];
                #pragma unroll
                for (int i = 0; i < 3; i++) af[i] = red2(acc[i]);
                #pragma unroll
                for (int off = 8; off <= 16; off <<= 1)
                    #pragma unroll
                    for (int i = 0; i < 3; i++)
                        af[i] += __shfl_xor_sync(FULLMASK, af[i], off);
                if (lane < 8)
                    #pragma unroll
                    for (int i = 0; i < 3; i++)
                        smf[F_GIS + (wid * 3 + i) * 8 + lane] = af[i];
            }
            __syncthreads();

            // ========== Phase C: gate combine -> h_new + release publish ==========
            if (tid < 128) {
                int g = tid >> 4, c = tid & 15;
                const float* gis = smf + F_GIS;
                float rr = gis[c * 8 + g] + smf[F_BIH + c]
                         + ghs_cur[c * 8 + g] + smf[F_BHH + c];
                float zz = gis[(16 + c) * 8 + g] + smf[F_BIH + 16 + c]
                         + ghs_cur[(16 + c) * 8 + g] + smf[F_BHH + 16 + c];
                float in_ = gis[(32 + c) * 8 + g] + smf[F_BIH + 32 + c];
                float hn  = ghs_cur[(32 + c) * 8 + g] + smf[F_BHH + 32 + c];
                float r = 1.f / (1.f + __expf(-rr));
                float z = 1.f / (1.f + __expf(-zz));
                float nn = tanhf(in_ + r * hn);
                int k = ch0 + c, kc = k >> 2;
                float ho = smf[(oxsh_cur + g * 69 + xslot(kc)) * 4 + (k & 3)];
                float hv = (1.f - z) * nn + z * ho;
                __stcg(&hnew_buf[(size_t)(g0 + g) * 256 + k], hv);
                __stcg(&hx[((size_t)(g0 + g) * 512 + n) * 256 + k], hv);
            }
            __syncthreads();
            if (tid == 0) st_rel(&hflag[FIDX(gb, cb)], tag);
            // h-exchange window: warp 15 polls; teamG pre-gathers step s+1's
            // old edges (rows published <= step s-1, visible via phase-A
            // acquires) into carried registers.
            if (wid == 15) {
                if (lane < 16)
                    while ((int)(ld_acq(&hflag[FIDX(gb, lane)]) - tag) < 0) { }
                __syncwarp();
            } else if (wid < 8) {
                aG0 = make_float4(0.f,0.f,0.f,0.f); aG1 = aG0;
                if (step + 1 < 512) {
                    for (int i = 0; i < cntR; i++) {
                        int sel = (i < 32) ? i0R : i1R;
                        int row = __shfl_sync(FULLMASK, sel, i & 31);
                        const float4* yr = (const float4*)(ybuf + (size_t)row * 256);
                        aG0 = f4add(aG0, __ldcg(yr + lane));
                        aG1 = f4add(aG1, __ldcg(yr + 32 + lane));
                    }
                }
            }
            __syncthreads();                 // full h_new visible + gather done

            // reload h_new -> XSA
            {
                int g = tid >> 6, kc = tid & 63;
                sm4[O_XSA + g * 69 + xslot(kc)] =
                    __ldcg((const float4*)(hnew_buf + (size_t)(g0 + g) * 256) + kc);
            }
            __syncthreads();

            // ========== Phase D: M1 t = relu(W1 h_new + b1), row/warp ==========
            {
                const float4* xb = sm4 + O_XSA + gg * 69;
                const float4* wb = sm4 + O_W14 + wid * 64;
                u64 acc = 0ull;
                #pragma unroll
                for (int c = 0; c < 16; c++) {
                    float4 xv = xb[c * 4 + ks];
                    ulonglong2 xu = *reinterpret_cast<ulonglong2*>(&xv);
                    float4 wv = wb[c * 4 + ks];
                    ulonglong2 wu = *reinterpret_cast<ulonglong2*>(&wv);
                    fma2(acc, xu.x, wu.x);
                    fma2(acc, xu.y, wu.y);
                }
                float af = red2(acc);
                af += __shfl_xor_sync(FULLMASK, af, 8);
                af += __shfl_xor_sync(FULLMASK, af, 16);
                if (lane < 8)
                    __stcg(&tbuf[(size_t)(g0 + lane) * 256 + ch0 + wid],
                           fmaxf(af + smf[F_B1 + wid], 0.f));
            }
            __syncthreads();
            if (tid == 0) st_rel(&tflag[FIDX(gb, cb)], tag);
            if (wid == 0) {
                if (lane < 16)
                    while ((int)(ld_acq(&tflag[FIDX(gb, lane)]) - tag) < 0) { }
                __syncwarp();
            }
            __syncthreads();                 // full t visible

            // reload t -> XSA
            {
                int g = tid >> 6, kc = tid & 63;
                sm4[O_XSA + g * 69 + xslot(kc)] =
                    __ldcg((const float4*)(tbuf + (size_t)(g0 + g) * 256) + kc);
            }
            __syncthreads();

            // ========== Phase E: M2 y = relu(W2 t + b2) + release publish ==========
            {
                const float4* xb = sm4 + O_XSA + gg * 69;
                const float4* wb = sm4 + O_W24 + wid * 64;
                u64 acc = 0ull;
                #pragma unroll
                for (int c = 0; c < 16; c++) {
                    float4 xv = xb[c * 4 + ks];
                    ulonglong2 xu = *reinterpret_cast<ulonglong2*>(&xv);
                    float4 wv = wb[c * 4 + ks];
                    ulonglong2 wu = *reinterpret_cast<ulonglong2*>(&wv);
                    fma2(acc, xu.x, wu.x);
                    fma2(acc, xu.y, wu.y);
                }
                float af = red2(acc);
                af += __shfl_xor_sync(FULLMASK, af, 8);
                af += __shfl_xor_sync(FULLMASK, af, 16);
                if (lane < 8)
                    __stcg(&ybuf[((size_t)(g0 + lane) * 512 + n) * 256 + ch0 + wid],
                           fmaxf(af + smf[F_B2 + wid], 0.f));
            }
            __syncthreads();
            if (tid == 0) st_rel(&yflag[FIDX(gb, cb)], tag);
            // no wait here: next step's teamG polls yflag per-warp
        }
    }
}

extern "C" void kernel_launch(void* const* d_in, const int* in_sizes, int n_in,
                              void* d_out, int out_size) {
    const float* x    = (const float*)d_in[0];
    const float* W1   = (const float*)d_in[1];
    const float* b1   = (const float*)d_in[2];
    const float* W2   = (const float*)d_in[3];
    const float* b2   = (const float*)d_in[4];
    const float* w_ih = (const float*)d_in[5];
    const float* b_ih = (const float*)d_in[6];
    const float* w_hh = (const float*)d_in[7];
    const float* b_hh = (const float*)d_in[8];
    const int*   src_f = (const int*)d_in[9];
    const int*   gid_f = (const int*)d_in[10];
    const float* msk_f = (const float*)d_in[11];
    const int*   src_b = (const int*)d_in[12];
    const int*   gid_b = (const int*)d_in[13];
    const float* msk_b = (const float*)d_in[14];
    float* hx = (float*)d_out;

    int Kf = in_sizes[9] / 512;
    int Kb = in_sizes[12] / 512;

    cudaMemcpyAsync(hx, x, (size_t)32768 * 256 * sizeof(float),
                    cudaMemcpyDeviceToDevice);

    cudaFuncSetAttribute(gnn_kernel, cudaFuncAttributeMaxDynamicSharedMemorySize,
                         SMEM_BYTES);
    gnn_kernel<<<128, 512, SMEM_BYTES>>>(hx, W1, b1, W2, b2, w_ih, b_ih, w_hh, b_hh,
                                         src_f, gid_f, msk_f, src_b, gid_b, msk_b,
                                         Kf, Kb);
}